// round 15
// baseline (speedup 1.0000x reference)
#include <cuda_runtime.h>
#include <math.h>

#define GRID 128
#define NT   256
#define Bz   32
#define Sz   256
#define Iz   256
#define Hz   512
#define Nz   128
#define Cz   64
#define Oz   256
#define Pz   268
#define KV   832
#define KVP  836
#define MP   68
#define EPSF 1e-8f
#define SMEM_BYTES 223312

struct GState {
    unsigned flags[GRID];
    unsigned pad[32];
    float h[Bz * Hz];
    float r[Bz * Cz];
    float p[Bz * Pz];
    float outh[Bz * Oz];
};
__device__ GState gs;

extern __shared__ __align__(16) float sm[];

__device__ __forceinline__ float sg_(float x) { return 1.f / (1.f + expf(-x)); }
__device__ __forceinline__ float sp_(float x) { return (x > 20.f) ? x : log1pf(expf(x)); }

__device__ __forceinline__ unsigned long long ffma2_(unsigned long long a,
                                                     unsigned long long b,
                                                     unsigned long long c) {
    unsigned long long d;
    asm("fma.rn.f32x2 %0, %1, %2, %3;" : "=l"(d) : "l"(a), "l"(b), "l"(c));
    return d;
}
__device__ __forceinline__ float hsum2_(unsigned long long v) {
    float lo, hi;
    asm("mov.b64 {%0, %1}, %2;" : "=f"(lo), "=f"(hi) : "l"(v));
    return lo + hi;
}
// V row base (16 batches): batches 8..15 get +4 word skew
__device__ __forceinline__ int voffb(int b) { return b * KVP + ((b >= 8) ? 4 : 0); }

// one warp polls 4 flags/lane with a single LDG.128
__device__ __forceinline__ void poll4(unsigned target, int tid, int nlanes) {
    if (tid < nlanes) {
        const unsigned* fp = &gs.flags[tid * 4];
        for (;;) {
            unsigned a, b, c, d;
            asm volatile("ld.volatile.global.v4.u32 {%0,%1,%2,%3}, [%4];"
                         : "=r"(a), "=r"(b), "=r"(c), "=r"(d) : "l"(fp));
            if ((int)(a - target) >= 0 && (int)(b - target) >= 0 &&
                (int)(c - target) >= 0 && (int)(d - target) >= 0) break;
        }
    }
}
__device__ __forceinline__ void gbar_full(unsigned target, int tid, int bx) {
    __syncthreads();
    if (tid == 0) { __threadfence(); atomicExch(&gs.flags[bx], target); }
    poll4(target, tid, 32);
    __threadfence();
    __syncthreads();
}
// everyone arrives; only batch CTAs wait (flags[0..63] cover all p producers)
__device__ __forceinline__ void gbar_p(unsigned target, int tid, int bx, bool isb) {
    __syncthreads();
    if (tid == 0) { __threadfence(); atomicExch(&gs.flags[bx], target); }
    if (isb) { poll4(target, tid, 16); __threadfence(); }
    __syncthreads();
}

__device__ __forceinline__ float grp_max128(float v, float* red, int tid) {
    #pragma unroll
    for (int o = 16; o > 0; o >>= 1) v = fmaxf(v, __shfl_xor_sync(0xffffffffu, v, o));
    int g4 = (tid >> 7) * 4;
    if ((tid & 31) == 0) red[g4 + ((tid >> 5) & 3)] = v;
    __syncthreads();
    float m = fmaxf(fmaxf(red[g4 + 0], red[g4 + 1]), fmaxf(red[g4 + 2], red[g4 + 3]));
    __syncthreads();
    return m;
}
__device__ __forceinline__ float grp_sum128(float v, float* red, int tid) {
    #pragma unroll
    for (int o = 16; o > 0; o >>= 1) v += __shfl_xor_sync(0xffffffffu, v, o);
    int g4 = (tid >> 7) * 4;
    if ((tid & 31) == 0) red[g4 + ((tid >> 5) & 3)] = v;
    __syncthreads();
    float m = (red[g4 + 0] + red[g4 + 1]) + (red[g4 + 2] + red[g4 + 3]);
    __syncthreads();
    return m;
}

// Gates GEMM pass over 16 batches (2 octets). 256 threads = NKQ x 2oct x RT.
// RPT=2 processes rows rowg and rowg+RT. Partials: gbuf[(kq*RT*RPT + row)*17 + b].
template<int NKQ, int RT, int RPT, int KLEN>
__device__ __forceinline__ void gemmA3(const float* __restrict__ WAp,
                                       const float* __restrict__ V,
                                       float* __restrict__ gbuf,
                                       int tid, int k0, bool accum)
{
    const int kq   = tid / (2 * RT);
    const int rem  = tid - kq * (2 * RT);
    const int oct  = rem / RT;
    const int rowg = rem - oct * RT;
    const int kb   = k0 + kq * KLEN;
    const float* Vb  = V + oct * (8 * KVP + 4) + kb;
    const float* Wp0 = WAp + rowg * KVP + kb;
    const float* Wp1 = WAp + (rowg + RT) * KVP + kb;
    unsigned long long a0[8], a1[8];
    #pragma unroll
    for (int j = 0; j < 8; j++) { a0[j] = 0ull; a1[j] = 0ull; }
    #pragma unroll 4
    for (int k = 0; k < KLEN; k += 4) {
        ulonglong2 w0 = *(const ulonglong2*)(Wp0 + k);
        ulonglong2 w1;
        if (RPT == 2) w1 = *(const ulonglong2*)(Wp1 + k);
        #pragma unroll
        for (int j = 0; j < 8; j++) {
            ulonglong2 v = *(const ulonglong2*)(Vb + j * KVP + k);
            a0[j] = ffma2_(w0.x, v.x, a0[j]);
            a0[j] = ffma2_(w0.y, v.y, a0[j]);
            if (RPT == 2) {
                a1[j] = ffma2_(w1.x, v.x, a1[j]);
                a1[j] = ffma2_(w1.y, v.y, a1[j]);
            }
        }
    }
    {
        float* gp = &gbuf[(kq * RT * RPT + rowg) * 17 + oct * 8];
        #pragma unroll
        for (int j = 0; j < 8; j++) { float s = hsum2_(a0[j]); gp[j] = accum ? gp[j] + s : s; }
    }
    if (RPT == 2) {
        float* gp = &gbuf[(kq * RT * RPT + rowg + RT) * 17 + oct * 8];
        #pragma unroll
        for (int j = 0; j < 8; j++) { float s = hsum2_(a1[j]); gp[j] = accum ? gp[j] + s : s; }
    }
}

__global__ void __launch_bounds__(NT, 1)
ntm_kernel(const float* __restrict__ X,
           const float* __restrict__ Wih, const float* __restrict__ Whh,
           const float* __restrict__ bl,
           const float* __restrict__ Whd, const float* __restrict__ bhd,
           const float* __restrict__ Wout, const float* __restrict__ bout,
           float* __restrict__ Y)
{
    const int tid = threadIdx.x, bx = blockIdx.x;
    const bool isb = (bx < Bz);
    const int nunits = isb ? 2 : 10;
    const int nrows  = 4 * nunits;            // 8 / 40 gate rows per CTA
    const int u_base = isb ? ((bx >> 1) * 2) : (Bz + ((bx - Bz) >> 1) * 10);
    const int b0 = (bx & 1) * 16;

    // ---- runtime smem layout (floats) ----
    float* WA  = sm;                          // nrows*KVP
    float* V   = WA + nrows * KVP;            // 16*KVP + 8
    float* gbA = V + (16 * KVP + 8);          // 8*32*17 = 4352 (non-batch pass1)
    float* gbB = gbA + 4352;                  // 16*8*17 = 2176 (pass2 / batch)
    float* bA  = gbB + 2176;                  // 40
    float* bB  = bA + 40;                     // 12
    float* cst = bB + 12;                     // 160
    float* red = cst + 160;                   // 8
    float* scb = red + 8;                     // 16
    float* tail = scb + 16;
    // batch tail
    float* M  = tail;                float* Mn = M + Nz * MP;
    float* wr = Mn + Nz;             float* ww = wr + Nz;
    float* t1 = ww + Nz;             float* pb = t1 + 256;
    float* kr = pb + Pz;             float* kw = kr + Cz;
    float* eb = kw + Cz;             float* ab = eb + Cz;
    // non-batch tail
    float* rbuf = tail;              // 64*32
    float* WoR  = rbuf + 2048;       // 3*64

    // ---------------- one-time staging ----------------
    for (int rr = 0; rr < nrows; rr++) {
        int q = rr / nunits, j = rr - q * nunits;
        int gr = q * Hz + u_base + j;
        for (int k = tid; k < KV; k += NT) {
            float v;
            if (k < 256)      v = Wih[gr * 320 + k];
            else if (k < 768) v = Whh[gr * Hz + (k - 256)];
            else              v = Wih[gr * 320 + 256 + (k - 768)];
            WA[rr * KVP + k] = v;
        }
    }
    if (tid < nrows) {
        int q = tid / nunits, j = tid - q * nunits;
        bA[tid] = bl[q * Hz + u_base + j];
    }
    const int baseB = (bx >> 1) * 9;
    const int cnt = (baseB >= 524) ? 0 : ((524 - baseB < 9) ? (524 - baseB) : 9);
    if (tid < cnt) {
        int gr = baseB + tid;
        bB[tid] = (gr < Pz) ? bhd[gr] : bout[gr - Pz];
    }
    if (!isb) {
        for (int i = tid; i < 3 * Cz; i += NT) {
            int o = (bx - Bz) * 3 + (i >> 6);
            if (o < Oz) WoR[i] = Wout[o * 576 + 512 + (i & 63)];
        }
    }
    for (int i = tid; i < 16 * KVP + 8; i += NT) V[i] = 0.f;
    for (int i = tid; i < 160; i += NT) cst[i] = 0.f;
    if (isb) {
        for (int i = tid; i < Nz * Cz; i += NT) M[(i >> 6) * MP + (i & 63)] = 0.01f;
        if (tid < Nz) {
            float w0 = (tid == 0) ? 1.f : 0.f;
            wr[tid] = w0; ww[tid] = w0; Mn[tid] = 0.08f;
        }
    }
    unsigned gen0 = *((volatile unsigned*)&gs.flags[bx]);
    unsigned nb = 0;
    __syncthreads();

    // ---------------- prologue: stage x(0); A-main(0) over k in [0,768) ----------------
    for (int i = tid; i < 16 * Iz / 4; i += NT) {
        int b = i >> 6, c4 = (i & 63) << 2;
        *(float4*)&V[voffb(b) + c4] =
            *(const float4*)&X[((size_t)(b0 + b) * Sz + 0) * Iz + c4];
    }
    __syncthreads();
    if (isb) {
        gemmA3<16, 8, 1, 48>(WA, V, gbB, tid, 0, false);
    } else {
        gemmA3<8, 16, 2, 96>(WA, V, gbA, tid, 0, false);
        gemmA3<16, 8, 1, 48>(WA + 32 * KVP, V, gbB, tid, 0, false);
    }
    __syncthreads();

    // ---------------- recurrence ----------------
    for (int t = 0; t < Sz; t++) {
        // == phase 1: stage x(t+1); stage r(t-1) ==
        if (t + 1 < Sz) {
            for (int i = tid; i < 16 * Iz / 4; i += NT) {
                int b = i >> 6, c4 = (i & 63) << 2;
                *(float4*)&V[voffb(b) + c4] =
                    *(const float4*)&X[((size_t)(b0 + b) * Sz + (t + 1)) * Iz + c4];
            }
        }
        if (t > 0) {
            {
                int b = tid >> 4, c4 = (tid & 15) << 2;
                *(float4*)&V[voffb(b) + 768 + c4] =
                    *(const float4*)&gs.r[(b0 + b) * Cz + c4];
            }
        }
        __syncthreads();
        // == phase 2: r-part of gates over k in [768,832) (accumulate) ==
        if (isb) {
            gemmA3<16, 8, 1, 4>(WA, V, gbB, tid, 768, true);
        } else {
            gemmA3<8, 16, 2, 8>(WA, V, gbA, tid, 768, true);
            gemmA3<16, 8, 1, 4>(WA + 32 * KVP, V, gbB, tid, 768, true);
        }
        __syncthreads();
        // == phase 3: LSTM; non-batch: D(t-1) ==
        if (tid < nunits * 16) {
            int j = tid >> 4, b = tid & 15;
            float G[4];
            #pragma unroll
            for (int g = 0; g < 4; g++) {
                int rr = g * nunits + j;
                float acc = bA[rr];
                if (isb) {
                    #pragma unroll
                    for (int kq = 0; kq < 16; kq++) acc += gbB[(kq * 8 + rr) * 17 + b];
                } else if (rr < 32) {
                    #pragma unroll
                    for (int kq = 0; kq < 8; kq++) acc += gbA[(kq * 32 + rr) * 17 + b];
                } else {
                    #pragma unroll
                    for (int kq = 0; kq < 16; kq++) acc += gbB[(kq * 8 + rr - 32) * 17 + b];
                }
                G[g] = acc;
            }
            float c = sg_(G[1]) * cst[tid] + sg_(G[0]) * tanhf(G[2]);
            float h = sg_(G[3]) * tanhf(c);
            cst[tid] = c;
            gs.h[(b0 + b) * Hz + u_base + j] = h;
        }
        if (!isb && t > 0) {
            for (int i = tid; i < Bz * Cz / 4; i += NT) {
                int b = i >> 4, c4 = (i & 15) << 2;
                float4 rv = *(const float4*)&gs.r[b * Cz + c4];
                rbuf[(c4 + 0) * 32 + b] = rv.x;
                rbuf[(c4 + 1) * 32 + b] = rv.y;
                rbuf[(c4 + 2) * 32 + b] = rv.z;
                rbuf[(c4 + 3) * 32 + b] = rv.w;
            }
            __syncthreads();
            if (tid < 96) {
                int oi = tid >> 5, b = tid & 31, o = (bx - Bz) * 3 + oi;
                if (o < Oz) {
                    float a0 = 0.f, a1 = 0.f;
                    const float* wo = &WoR[oi * Cz];
                    #pragma unroll
                    for (int c = 0; c < 64; c += 2) {
                        a0 = fmaf(rbuf[c * 32 + b], wo[c], a0);
                        a1 = fmaf(rbuf[(c + 1) * 32 + b], wo[c + 1], a1);
                    }
                    Y[((size_t)b * Sz + (t - 1)) * Oz + o] = gs.outh[b * Oz + o] + a0 + a1;
                }
            }
        }
        gbar_full(gen0 + (++nb), tid, bx);   // bar1: h(t)

        // == phase 5: stage h (this CTA's 16 batches); B(t), W streamed from L2 ==
        for (int i = tid; i < 16 * Hz / 4; i += NT) {
            int b = i >> 7, c4 = (i & 127) << 2;
            *(float4*)&V[voffb(b) + 256 + c4] =
                *(const float4*)&gs.h[(b0 + b) * Hz + c4];
        }
        __syncthreads();
        if (tid < cnt * 16) {
            int rr = tid >> 4, b = tid & 15;
            int gr = baseB + rr;
            const ulonglong2* Wp = (const ulonglong2*)
                ((gr < Pz) ? (Whd + (size_t)gr * Hz) : (Wout + (size_t)(gr - Pz) * 576));
            const ulonglong2* hp = (const ulonglong2*)&V[voffb(b) + 256];
            unsigned long long q0 = 0ull, q1 = 0ull, q2 = 0ull, q3 = 0ull;
            #pragma unroll 4
            for (int i = 0; i < 128; i += 2) {
                ulonglong2 w = Wp[i], v = hp[i];
                q0 = ffma2_(w.x, v.x, q0);
                q1 = ffma2_(w.y, v.y, q1);
                w = Wp[i + 1]; v = hp[i + 1];
                q2 = ffma2_(w.x, v.x, q2);
                q3 = ffma2_(w.y, v.y, q3);
            }
            float acc = (hsum2_(q0) + hsum2_(q1)) + (hsum2_(q2) + hsum2_(q3)) + bB[rr];
            if (gr < Pz) gs.p[(b0 + b) * Pz + gr] = acc;
            else         gs.outh[(b0 + b) * Oz + (gr - Pz)] = acc;
        }
        gbar_p(gen0 + (++nb), tid, bx, isb); // bar2: p (batch waits only)

        // == phase 7: batch: C(t); then all: A-main(t+1) ==
        if (isb) {
            for (int i = tid; i < Pz; i += NT) pb[i] = gs.p[bx * Pz + i];
            __syncthreads();
            if (tid < 64) {
                kr[tid] = pb[tid];
                kw[tid] = pb[70 + tid];
                eb[tid] = sg_(pb[140 + tid]);
                ab[tid] = pb[204 + tid];
            }
            if ((tid & 127) == 0) {
                int hh = tid >> 7, o = hh ? 70 : 0;
                float kn0 = 0.f, kn1 = 0.f;
                for (int c = 0; c < 64; c += 2) {
                    kn0 = fmaf(pb[o + c], pb[o + c], kn0);
                    kn1 = fmaf(pb[o + c + 1], pb[o + c + 1], kn1);
                }
                float kn = sqrtf(kn0 + kn1);
                float s0 = pb[o + 66], s1 = pb[o + 67], s2 = pb[o + 68];
                float mx = fmaxf(s0, fmaxf(s1, s2));
                float e0 = expf(s0 - mx), e1 = expf(s1 - mx), e2 = expf(s2 - mx);
                float inv = 1.f / (e0 + e1 + e2);
                float* c_ = &scb[hh * 8];
                c_[0] = sp_(pb[o + 64]);
                c_[1] = sg_(pb[o + 65]);
                c_[2] = e0 * inv; c_[3] = e1 * inv; c_[4] = e2 * inv;
                c_[5] = 1.f + sp_(pb[o + 69]);
                c_[6] = 1.f / (kn + EPSF);
            }
            __syncthreads();
            {
                const int hh = tid >> 7, n = tid & 127;
                const float* kk = hh ? kw : kr;
                float* wprev = hh ? ww : wr;
                const float* c_ = &scb[hh * 8];
                float* t1h = &t1[hh * Nz];
                float d0 = 0.f, d1 = 0.f, d2 = 0.f, d3 = 0.f;
                const float* Mp = &M[n * MP];
                #pragma unroll
                for (int c = 0; c < 64; c += 16) {
                    float4 m, k4;
                    m = *(const float4*)(Mp + c);      k4 = *(const float4*)(kk + c);
                    d0 = fmaf(m.x, k4.x, d0); d0 = fmaf(m.y, k4.y, d0);
                    d0 = fmaf(m.z, k4.z, d0); d0 = fmaf(m.w, k4.w, d0);
                    m = *(const float4*)(Mp + c + 4);  k4 = *(const float4*)(kk + c + 4);
                    d1 = fmaf(m.x, k4.x, d1); d1 = fmaf(m.y, k4.y, d1);
                    d1 = fmaf(m.z, k4.z, d1); d1 = fmaf(m.w, k4.w, d1);
                    m = *(const float4*)(Mp + c + 8);  k4 = *(const float4*)(kk + c + 8);
                    d2 = fmaf(m.x, k4.x, d2); d2 = fmaf(m.y, k4.y, d2);
                    d2 = fmaf(m.z, k4.z, d2); d2 = fmaf(m.w, k4.w, d2);
                    m = *(const float4*)(Mp + c + 12); k4 = *(const float4*)(kk + c + 12);
                    d3 = fmaf(m.x, k4.x, d3); d3 = fmaf(m.y, k4.y, d3);
                    d3 = fmaf(m.z, k4.z, d3); d3 = fmaf(m.w, k4.w, d3);
                }
                float d = (d0 + d1) + (d2 + d3);
                float val = c_[0] * d / (Mn[n] + EPSF) * c_[6];
                float mx = grp_max128(val, red, tid);
                float ex = expf(val - mx);
                float sum = grp_sum128(ex, red, tid);
                float wc = ex / sum;
                t1h[n] = c_[1] * wc + (1.f - c_[1]) * wprev[n];
                __syncthreads();
                float ws = c_[2] * t1h[(n + 1) & 127]
                         + c_[3] * t1h[n]
                         + c_[4] * t1h[(n + 127) & 127];
                float wp = powf(ws + EPSF, c_[5]);
                float sw = grp_sum128(wp, red, tid);
                wprev[n] = wp / sw;
            }
            __syncthreads();
            if (tid < 128) {
                float wwn = ww[tid];
                float* Mp = &M[tid * MP];
                float n0 = 0.f, n1 = 0.f;
                #pragma unroll
                for (int c = 0; c < 64; c += 2) {
                    float m0 = Mp[c] * (1.f - wwn * eb[c]) + wwn * ab[c];
                    float m1 = Mp[c + 1] * (1.f - wwn * eb[c + 1]) + wwn * ab[c + 1];
                    Mp[c] = m0; Mp[c + 1] = m1;
                    n0 = fmaf(m0, m0, n0); n1 = fmaf(m1, m1, n1);
                }
                Mn[tid] = sqrtf(n0 + n1);
            }
            __syncthreads();
            {
                int q = tid >> 6, c = tid & 63;
                float a0 = 0.f, a1 = 0.f;
                #pragma unroll
                for (int n2 = 0; n2 < 32; n2 += 2) {
                    a0 = fmaf(wr[q * 32 + n2], M[(q * 32 + n2) * MP + c], a0);
                    a1 = fmaf(wr[q * 32 + n2 + 1], M[(q * 32 + n2 + 1) * MP + c], a1);
                }
                t1[q * 64 + c] = a0 + a1;
            }
            __syncthreads();
            if (tid < 64)
                gs.r[bx * Cz + tid] = (t1[tid] + t1[64 + tid]) + (t1[128 + tid] + t1[192 + tid]);
        }
        if (t + 1 < Sz) {
            if (isb) {
                gemmA3<16, 8, 1, 48>(WA, V, gbB, tid, 0, false);
            } else {
                gemmA3<8, 16, 2, 96>(WA, V, gbA, tid, 0, false);
                gemmA3<16, 8, 1, 48>(WA + 32 * KVP, V, gbB, tid, 0, false);
            }
        }
        gbar_full(gen0 + (++nb), tid, bx);   // bar3: r(t)
    }

    // ---------------- epilogue: D(255) ----------------
    if (!isb) {
        for (int i = tid; i < Bz * Cz / 4; i += NT) {
            int b = i >> 4, c4 = (i & 15) << 2;
            float4 rv = *(const float4*)&gs.r[b * Cz + c4];
            rbuf[(c4 + 0) * 32 + b] = rv.x;
            rbuf[(c4 + 1) * 32 + b] = rv.y;
            rbuf[(c4 + 2) * 32 + b] = rv.z;
            rbuf[(c4 + 3) * 32 + b] = rv.w;
        }
        __syncthreads();
        if (tid < 96) {
            int oi = tid >> 5, b = tid & 31, o = (bx - Bz) * 3 + oi;
            if (o < Oz) {
                float a0 = 0.f, a1 = 0.f;
                const float* wo = &WoR[oi * Cz];
                #pragma unroll
                for (int c = 0; c < 64; c += 2) {
                    a0 = fmaf(rbuf[c * 32 + b], wo[c], a0);
                    a1 = fmaf(rbuf[(c + 1) * 32 + b], wo[c + 1], a1);
                }
                Y[((size_t)b * Sz + (Sz - 1)) * Oz + o] = gs.outh[b * Oz + o] + a0 + a1;
            }
        }
    }
}

extern "C" void kernel_launch(void* const* d_in, const int* in_sizes, int n_in,
                              void* d_out, int out_size) {
    (void)in_sizes; (void)n_in; (void)out_size;
    const float* X    = (const float*)d_in[0];
    const float* Wih  = (const float*)d_in[1];
    const float* Whh  = (const float*)d_in[2];
    const float* bl   = (const float*)d_in[3];
    const float* Whd  = (const float*)d_in[4];
    const float* bhd  = (const float*)d_in[5];
    const float* Wout = (const float*)d_in[6];
    const float* bout = (const float*)d_in[7];
    float* Y = (float*)d_out;

    cudaFuncSetAttribute(ntm_kernel, cudaFuncAttributeMaxDynamicSharedMemorySize,
                         SMEM_BYTES);
    ntm_kernel<<<GRID, NT, SMEM_BYTES>>>(X, Wih, Whh, bl, Whd, bhd, Wout, bout, Y);
}

// round 16
// speedup vs baseline: 1.1889x; 1.1889x over previous
#include <cuda_runtime.h>
#include <math.h>

#define GRID 128
#define NT   256
#define Bz   32
#define Sz   256
#define Iz   256
#define Hz   512
#define Nz   128
#define Cz   64
#define Oz   256
#define Pz   268
#define KV   832
#define KVP  836
#define WBP  516
#define MP   68
#define EPSF 1e-8f
#define SMEM_BYTES 224992

struct GState {
    unsigned flags[GRID];
    unsigned pad[32];
    float h[Bz * Hz];
    float r[Bz * Cz];
    float p[Bz * Pz];
    float outh[Bz * Oz];
};
__device__ GState gs;

extern __shared__ __align__(16) float sm[];

__device__ __forceinline__ float sg_(float x) { return 1.f / (1.f + expf(-x)); }
__device__ __forceinline__ float sp_(float x) { return (x > 20.f) ? x : log1pf(expf(x)); }

__device__ __forceinline__ unsigned long long ffma2_(unsigned long long a,
                                                     unsigned long long b,
                                                     unsigned long long c) {
    unsigned long long d;
    asm("fma.rn.f32x2 %0, %1, %2, %3;" : "=l"(d) : "l"(a), "l"(b), "l"(c));
    return d;
}
__device__ __forceinline__ float hsum2_(unsigned long long v) {
    float lo, hi;
    asm("mov.b64 {%0, %1}, %2;" : "=f"(lo), "=f"(hi) : "l"(v));
    return lo + hi;
}
// V row base (16 batches): batches 8..15 get +4 word skew
__device__ __forceinline__ int voffb(int b) { return b * KVP + ((b >= 8) ? 4 : 0); }

// R12-style barrier: every CTA publishes its epoch; 128 threads each poll one flag.
__device__ __forceinline__ void gbar_full(unsigned target, int tid, int bx) {
    __syncthreads();
    if (tid == 0) { __threadfence(); atomicExch(&gs.flags[bx], target); }
    if (tid < GRID) {
        volatile unsigned* f = &gs.flags[tid];
        while ((int)(*f - target) < 0) {}
    }
    __threadfence();
    __syncthreads();
}
// bar2: everyone arrives; only batch CTAs wait, and only on the p-producers (bx 0..63).
__device__ __forceinline__ void gbar_p(unsigned target, int tid, int bx, bool isb) {
    __syncthreads();
    if (tid == 0) { __threadfence(); atomicExch(&gs.flags[bx], target); }
    if (isb) {
        if (tid < 64) {
            volatile unsigned* f = &gs.flags[tid];
            while ((int)(*f - target) < 0) {}
        }
        __threadfence();
    }
    __syncthreads();
}

__device__ __forceinline__ float grp_max128(float v, float* red, int tid) {
    #pragma unroll
    for (int o = 16; o > 0; o >>= 1) v = fmaxf(v, __shfl_xor_sync(0xffffffffu, v, o));
    int g4 = (tid >> 7) * 4;
    if ((tid & 31) == 0) red[g4 + ((tid >> 5) & 3)] = v;
    __syncthreads();
    float m = fmaxf(fmaxf(red[g4 + 0], red[g4 + 1]), fmaxf(red[g4 + 2], red[g4 + 3]));
    __syncthreads();
    return m;
}
__device__ __forceinline__ float grp_sum128(float v, float* red, int tid) {
    #pragma unroll
    for (int o = 16; o > 0; o >>= 1) v += __shfl_xor_sync(0xffffffffu, v, o);
    int g4 = (tid >> 7) * 4;
    if ((tid & 31) == 0) red[g4 + ((tid >> 5) & 3)] = v;
    __syncthreads();
    float m = (red[g4 + 0] + red[g4 + 1]) + (red[g4 + 2] + red[g4 + 3]);
    __syncthreads();
    return m;
}

// Gates GEMM pass over 16 batches (2 octets) on threads [TID0, TID0 + NKQ*2*RT).
// RPT=2 also processes row rowg+RT. Partials: gbuf[(kq*RT*RPT + row)*17 + oct*8 + j].
template<int NKQ, int RT, int RPT, int TID0>
__device__ __forceinline__ void gemmA(const float* __restrict__ WAp,
                                      const float* __restrict__ V,
                                      float* __restrict__ gbuf,
                                      int tid, int k0, int klen, bool accum)
{
    const int tt = tid - TID0;
    if (tt < 0 || tt >= NKQ * 2 * RT) return;
    const int kq   = tt / (2 * RT);
    const int rem  = tt - kq * (2 * RT);
    const int oct  = rem / RT;
    const int rowg = rem - oct * RT;
    const int kb   = k0 + kq * klen;
    const float* Vb  = V + oct * (8 * KVP + 4) + kb;
    const float* Wp0 = WAp + rowg * KVP + kb;
    const float* Wp1 = WAp + (rowg + RT) * KVP + kb;
    unsigned long long a0[8], a1[8];
    #pragma unroll
    for (int j = 0; j < 8; j++) { a0[j] = 0ull; a1[j] = 0ull; }
    #pragma unroll 4
    for (int k = 0; k < klen; k += 4) {
        ulonglong2 w0 = *(const ulonglong2*)(Wp0 + k);
        ulonglong2 w1;
        if (RPT == 2) w1 = *(const ulonglong2*)(Wp1 + k);
        #pragma unroll
        for (int j = 0; j < 8; j++) {
            ulonglong2 v = *(const ulonglong2*)(Vb + j * KVP + k);
            a0[j] = ffma2_(w0.x, v.x, a0[j]);
            a0[j] = ffma2_(w0.y, v.y, a0[j]);
            if (RPT == 2) {
                a1[j] = ffma2_(w1.x, v.x, a1[j]);
                a1[j] = ffma2_(w1.y, v.y, a1[j]);
            }
        }
    }
    {
        float* gp = &gbuf[(kq * RT * RPT + rowg) * 17 + oct * 8];
        #pragma unroll
        for (int j = 0; j < 8; j++) { float s = hsum2_(a0[j]); gp[j] = accum ? gp[j] + s : s; }
    }
    if (RPT == 2) {
        float* gp = &gbuf[(kq * RT * RPT + rowg + RT) * 17 + oct * 8];
        #pragma unroll
        for (int j = 0; j < 8; j++) { float s = hsum2_(a1[j]); gp[j] = accum ? gp[j] + s : s; }
    }
}

__global__ void __launch_bounds__(NT, 1)
ntm_kernel(const float* __restrict__ X,
           const float* __restrict__ Wih, const float* __restrict__ Whh,
           const float* __restrict__ bl,
           const float* __restrict__ Whd, const float* __restrict__ bhd,
           const float* __restrict__ Wout, const float* __restrict__ bout,
           float* __restrict__ Y)
{
    const int tid = threadIdx.x, bx = blockIdx.x;
    const bool isb = (bx < Bz);
    const int nunits = isb ? 2 : 10;
    const int nrows  = 4 * nunits;            // 8 / 40 gate rows per CTA
    const int u_base = isb ? ((bx >> 1) * 2) : (Bz + ((bx - Bz) >> 1) * 10);
    const int b0 = (bx & 1) * 16;

    // ---- runtime smem layout (floats) ----
    float* WA  = sm;                          // nrows*KVP (max 33440)
    float* V   = WA + nrows * KVP;            // 13384
    float* gbA = V + 13384;                   // 2176 (non-batch pass1; aliased as rbuf in D)
    float* gbB = gbA + 2176;                  // 2176 (pass2 / batch main)
    float* WB  = gbB + 2176;                  // 4644
    float* bA  = WB + 4644;                   // 40
    float* bB  = bA + 40;                     // 12
    float* cst = bB + 12;                     // 160
    float* red = cst + 160;                   // 8
    float* scb = red + 8;                     // 16
    float* WoR = scb + 16;                    // 192
    float* tail = WoR + 192;
    // batch tail
    float* M  = tail;                float* Mn = M + Nz * MP;
    float* wr = Mn + Nz;             float* ww = wr + Nz;
    float* t1 = ww + Nz;             float* pb = t1 + 256;
    float* kr = pb + Pz;             float* kw = kr + Cz;
    float* eb = kw + Cz;             float* ab = eb + Cz;
    // non-batch: rbuf aliases gbA (dead between LSTM-consume and next A-main write)
    float* rbuf = gbA;

    // ---------------- one-time staging ----------------
    for (int rr = 0; rr < nrows; rr++) {
        int q = rr / nunits, j = rr - q * nunits;
        int gr = q * Hz + u_base + j;
        for (int k = tid; k < KV; k += NT) {
            float v;
            if (k < 256)      v = Wih[gr * 320 + k];
            else if (k < 768) v = Whh[gr * Hz + (k - 256)];
            else              v = Wih[gr * 320 + 256 + (k - 768)];
            WA[rr * KVP + k] = v;
        }
    }
    if (tid < nrows) {
        int q = tid / nunits, j = tid - q * nunits;
        bA[tid] = bl[q * Hz + u_base + j];
    }
    const int baseB = (bx >> 1) * 9;
    const int cnt = (baseB >= 524) ? 0 : ((524 - baseB < 9) ? (524 - baseB) : 9);
    for (int rr = 0; rr < cnt; rr++) {
        int gr = baseB + rr;
        for (int k = tid; k < Hz; k += NT)
            WB[rr * WBP + k] = (gr < Pz) ? Whd[gr * Hz + k] : Wout[(gr - Pz) * 576 + k];
    }
    if (tid < cnt) {
        int gr = baseB + tid;
        bB[tid] = (gr < Pz) ? bhd[gr] : bout[gr - Pz];
    }
    if (!isb) {
        for (int i = tid; i < 3 * Cz; i += NT) {
            int o = (bx - Bz) * 3 + (i >> 6);
            if (o < Oz) WoR[i] = Wout[o * 576 + 512 + (i & 63)];
        }
    }
    for (int i = tid; i < 13384; i += NT) V[i] = 0.f;
    for (int i = tid; i < 160; i += NT) cst[i] = 0.f;
    if (isb) {
        for (int i = tid; i < Nz * Cz; i += NT) M[(i >> 6) * MP + (i & 63)] = 0.01f;
        if (tid < Nz) {
            float w0 = (tid == 0) ? 1.f : 0.f;
            wr[tid] = w0; ww[tid] = w0; Mn[tid] = 0.08f;
        }
    }
    unsigned gen0 = *((volatile unsigned*)&gs.flags[bx]);
    unsigned nb = 0;
    __syncthreads();

    // ---------------- prologue: stage x(0); A-main(0) over k in [0,768) ----------------
    for (int i = tid; i < 16 * Iz / 4; i += NT) {
        int b = i >> 6, c4 = (i & 63) << 2;
        *(float4*)&V[voffb(b) + c4] =
            *(const float4*)&X[((size_t)(b0 + b) * Sz + 0) * Iz + c4];
    }
    __syncthreads();
    if (isb) {
        gemmA<16, 8, 1, 0>(WA, V, gbB, tid, 0, 48, false);
    } else {
        gemmA<4, 16, 2, 0>(WA, V, gbA, tid, 0, 192, false);          // rows 0..31
        gemmA<8, 8, 1, 128>(WA + 32 * KVP, V, gbB, tid, 0, 96, false); // rows 32..39
    }
    __syncthreads();

    // ---------------- recurrence ----------------
    for (int t = 0; t < Sz; t++) {
        // == phase 1: stage x(t+1); stage r(t-1) ==
        if (t + 1 < Sz) {
            for (int i = tid; i < 16 * Iz / 4; i += NT) {
                int b = i >> 6, c4 = (i & 63) << 2;
                *(float4*)&V[voffb(b) + c4] =
                    *(const float4*)&X[((size_t)(b0 + b) * Sz + (t + 1)) * Iz + c4];
            }
        }
        if (t > 0) {
            int b = tid >> 4, c4 = (tid & 15) << 2;
            *(float4*)&V[voffb(b) + 768 + c4] =
                *(const float4*)&gs.r[(b0 + b) * Cz + c4];
        }
        __syncthreads();
        // == phase 2: r-part of gates over k in [768,832) (accumulate) ==
        if (isb) {
            gemmA<16, 8, 1, 0>(WA, V, gbB, tid, 768, 4, true);
        } else {
            gemmA<4, 16, 2, 0>(WA, V, gbA, tid, 768, 16, true);
            gemmA<8, 8, 1, 128>(WA + 32 * KVP, V, gbB, tid, 768, 8, true);
        }
        __syncthreads();
        // == phase 3: LSTM; non-batch: D(t-1) using rbuf aliased on gbA ==
        if (tid < nunits * 16) {
            int j = tid >> 4, b = tid & 15;
            float G[4];
            #pragma unroll
            for (int g = 0; g < 4; g++) {
                int rr = g * nunits + j;
                float acc = bA[rr];
                if (isb) {
                    #pragma unroll
                    for (int kq = 0; kq < 16; kq++) acc += gbB[(kq * 8 + rr) * 17 + b];
                } else if (rr < 32) {
                    #pragma unroll
                    for (int kq = 0; kq < 4; kq++) acc += gbA[(kq * 32 + rr) * 17 + b];
                } else {
                    #pragma unroll
                    for (int kq = 0; kq < 8; kq++) acc += gbB[(kq * 8 + rr - 32) * 17 + b];
                }
                G[g] = acc;
            }
            float c = sg_(G[1]) * cst[tid] + sg_(G[0]) * tanhf(G[2]);
            float h = sg_(G[3]) * tanhf(c);
            cst[tid] = c;
            gs.h[(b0 + b) * Hz + u_base + j] = h;
        }
        if (!isb && t > 0) {
            __syncthreads();   // gbA partials fully consumed before rbuf overwrites
            for (int i = tid; i < Bz * Cz / 4; i += NT) {
                int b = i >> 4, c4 = (i & 15) << 2;
                float4 rv = *(const float4*)&gs.r[b * Cz + c4];
                rbuf[(c4 + 0) * 32 + b] = rv.x;
                rbuf[(c4 + 1) * 32 + b] = rv.y;
                rbuf[(c4 + 2) * 32 + b] = rv.z;
                rbuf[(c4 + 3) * 32 + b] = rv.w;
            }
            __syncthreads();
            if (tid < 96) {
                int oi = tid >> 5, b = tid & 31, o = (bx - Bz) * 3 + oi;
                if (o < Oz) {
                    float a0 = 0.f, a1 = 0.f;
                    const float* wo = &WoR[oi * Cz];
                    #pragma unroll
                    for (int c = 0; c < 64; c += 2) {
                        a0 = fmaf(rbuf[c * 32 + b], wo[c], a0);
                        a1 = fmaf(rbuf[(c + 1) * 32 + b], wo[c + 1], a1);
                    }
                    Y[((size_t)b * Sz + (t - 1)) * Oz + o] = gs.outh[b * Oz + o] + a0 + a1;
                }
            }
        }
        gbar_full(gen0 + (++nb), tid, bx);   // bar1: h(t)

        // == phase 5: stage h (this CTA's 16 batches); B(t) from smem WB ==
        for (int i = tid; i < 16 * Hz / 4; i += NT) {
            int b = i >> 7, c4 = (i & 127) << 2;
            *(float4*)&V[voffb(b) + 256 + c4] =
                *(const float4*)&gs.h[(b0 + b) * Hz + c4];
        }
        __syncthreads();
        if (tid < cnt * 16) {
            int rr = tid >> 4, b = tid & 15;
            const ulonglong2* Wp = (const ulonglong2*)&WB[rr * WBP];
            const ulonglong2* hp = (const ulonglong2*)&V[voffb(b) + 256];
            unsigned long long q0 = 0ull, q1 = 0ull, q2 = 0ull, q3 = 0ull;
            #pragma unroll 4
            for (int i = 0; i < 128; i += 2) {
                ulonglong2 w = Wp[i], v = hp[i];
                q0 = ffma2_(w.x, v.x, q0);
                q1 = ffma2_(w.y, v.y, q1);
                w = Wp[i + 1]; v = hp[i + 1];
                q2 = ffma2_(w.x, v.x, q2);
                q3 = ffma2_(w.y, v.y, q3);
            }
            float acc = (hsum2_(q0) + hsum2_(q1)) + (hsum2_(q2) + hsum2_(q3)) + bB[rr];
            int gr = baseB + rr;
            if (gr < Pz) gs.p[(b0 + b) * Pz + gr] = acc;
            else         gs.outh[(b0 + b) * Oz + (gr - Pz)] = acc;
        }
        gbar_p(gen0 + (++nb), tid, bx, isb); // bar2: p (batch waits only)

        // == phase 7: batch: C(t); then all: A-main(t+1) ==
        if (isb) {
            for (int i = tid; i < Pz; i += NT) pb[i] = gs.p[bx * Pz + i];
            __syncthreads();
            if (tid < 64) {
                kr[tid] = pb[tid];
                kw[tid] = pb[70 + tid];
                eb[tid] = sg_(pb[140 + tid]);
                ab[tid] = pb[204 + tid];
            }
            if ((tid & 127) == 0) {
                int hh = tid >> 7, o = hh ? 70 : 0;
                float kn0 = 0.f, kn1 = 0.f;
                for (int c = 0; c < 64; c += 2) {
                    kn0 = fmaf(pb[o + c], pb[o + c], kn0);
                    kn1 = fmaf(pb[o + c + 1], pb[o + c + 1], kn1);
                }
                float kn = sqrtf(kn0 + kn1);
                float s0 = pb[o + 66], s1 = pb[o + 67], s2 = pb[o + 68];
                float mx = fmaxf(s0, fmaxf(s1, s2));
                float e0 = expf(s0 - mx), e1 = expf(s1 - mx), e2 = expf(s2 - mx);
                float inv = 1.f / (e0 + e1 + e2);
                float* c_ = &scb[hh * 8];
                c_[0] = sp_(pb[o + 64]);
                c_[1] = sg_(pb[o + 65]);
                c_[2] = e0 * inv; c_[3] = e1 * inv; c_[4] = e2 * inv;
                c_[5] = 1.f + sp_(pb[o + 69]);
                c_[6] = 1.f / (kn + EPSF);
            }
            __syncthreads();
            {
                const int hh = tid >> 7, n = tid & 127;
                const float* kk = hh ? kw : kr;
                float* wprev = hh ? ww : wr;
                const float* c_ = &scb[hh * 8];
                float* t1h = &t1[hh * Nz];
                float d0 = 0.f, d1 = 0.f, d2 = 0.f, d3 = 0.f;
                const float* Mp = &M[n * MP];
                #pragma unroll
                for (int c = 0; c < 64; c += 16) {
                    float4 m, k4;
                    m = *(const float4*)(Mp + c);      k4 = *(const float4*)(kk + c);
                    d0 = fmaf(m.x, k4.x, d0); d0 = fmaf(m.y, k4.y, d0);
                    d0 = fmaf(m.z, k4.z, d0); d0 = fmaf(m.w, k4.w, d0);
                    m = *(const float4*)(Mp + c + 4);  k4 = *(const float4*)(kk + c + 4);
                    d1 = fmaf(m.x, k4.x, d1); d1 = fmaf(m.y, k4.y, d1);
                    d1 = fmaf(m.z, k4.z, d1); d1 = fmaf(m.w, k4.w, d1);
                    m = *(const float4*)(Mp + c + 8);  k4 = *(const float4*)(kk + c + 8);
                    d2 = fmaf(m.x, k4.x, d2); d2 = fmaf(m.y, k4.y, d2);
                    d2 = fmaf(m.z, k4.z, d2); d2 = fmaf(m.w, k4.w, d2);
                    m = *(const float4*)(Mp + c + 12); k4 = *(const float4*)(kk + c + 12);
                    d3 = fmaf(m.x, k4.x, d3); d3 = fmaf(m.y, k4.y, d3);
                    d3 = fmaf(m.z, k4.z, d3); d3 = fmaf(m.w, k4.w, d3);
                }
                float d = (d0 + d1) + (d2 + d3);
                float val = c_[0] * d / (Mn[n] + EPSF) * c_[6];
                float mx = grp_max128(val, red, tid);
                float ex = expf(val - mx);
                float sum = grp_sum128(ex, red, tid);
                float wc = ex / sum;
                t1h[n] = c_[1] * wc + (1.f - c_[1]) * wprev[n];
                __syncthreads();
                float ws = c_[2] * t1h[(n + 1) & 127]
                         + c_[3] * t1h[n]
                         + c_[4] * t1h[(n + 127) & 127];
                float wp = powf(ws + EPSF, c_[5]);
                float sw = grp_sum128(wp, red, tid);
                wprev[n] = wp / sw;
            }
            __syncthreads();
            if (tid < 128) {
                float wwn = ww[tid];
                float* Mp = &M[tid * MP];
                float n0 = 0.f, n1 = 0.f;
                #pragma unroll
                for (int c = 0; c < 64; c += 2) {
                    float m0 = Mp[c] * (1.f - wwn * eb[c]) + wwn * ab[c];
                    float m1 = Mp[c + 1] * (1.f - wwn * eb[c + 1]) + wwn * ab[c + 1];
                    Mp[c] = m0; Mp[c + 1] = m1;
                    n0 = fmaf(m0, m0, n0); n1 = fmaf(m1, m1, n1);
                }
                Mn[tid] = sqrtf(n0 + n1);
            }
            __syncthreads();
            {
                int q = tid >> 6, c = tid & 63;
                float a0 = 0.f, a1 = 0.f;
                #pragma unroll
                for (int n2 = 0; n2 < 32; n2 += 2) {
                    a0 = fmaf(wr[q * 32 + n2], M[(q * 32 + n2) * MP + c], a0);
                    a1 = fmaf(wr[q * 32 + n2 + 1], M[(q * 32 + n2 + 1) * MP + c], a1);
                }
                t1[q * 64 + c] = a0 + a1;
            }
            __syncthreads();
            if (tid < 64)
                gs.r[bx * Cz + tid] = (t1[tid] + t1[64 + tid]) + (t1[128 + tid] + t1[192 + tid]);
        }
        if (t + 1 < Sz) {
            if (isb) {
                gemmA<16, 8, 1, 0>(WA, V, gbB, tid, 0, 48, false);
            } else {
                gemmA<4, 16, 2, 0>(WA, V, gbA, tid, 0, 192, false);
                gemmA<8, 8, 1, 128>(WA + 32 * KVP, V, gbB, tid, 0, 96, false);
            }
        }
        gbar_full(gen0 + (++nb), tid, bx);   // bar3: r(t)
    }

    // ---------------- epilogue: D(255) ----------------
    if (!isb) {
        __syncthreads();
        for (int i = tid; i < Bz * Cz / 4; i += NT) {
            int b = i >> 4, c4 = (i & 15) << 2;
            float4 rv = *(const float4*)&gs.r[b * Cz + c4];
            rbuf[(c4 + 0) * 32 + b] = rv.x;
            rbuf[(c4 + 1) * 32 + b] = rv.y;
            rbuf[(c4 + 2) * 32 + b] = rv.z;
            rbuf[(c4 + 3) * 32 + b] = rv.w;
        }
        __syncthreads();
        if (tid < 96) {
            int oi = tid >> 5, b = tid & 31, o = (bx - Bz) * 3 + oi;
            if (o < Oz) {
                float a0 = 0.f, a1 = 0.f;
                const float* wo = &WoR[oi * Cz];
                #pragma unroll
                for (int c = 0; c < 64; c += 2) {
                    a0 = fmaf(rbuf[c * 32 + b], wo[c], a0);
                    a1 = fmaf(rbuf[(c + 1) * 32 + b], wo[c + 1], a1);
                }
                Y[((size_t)b * Sz + (Sz - 1)) * Oz + o] = gs.outh[b * Oz + o] + a0 + a1;
            }
        }
    }
}

extern "C" void kernel_launch(void* const* d_in, const int* in_sizes, int n_in,
                              void* d_out, int out_size) {
    (void)in_sizes; (void)n_in; (void)out_size;
    const float* X    = (const float*)d_in[0];
    const float* Wih  = (const float*)d_in[1];
    const float* Whh  = (const float*)d_in[2];
    const float* bl   = (const float*)d_in[3];
    const float* Whd  = (const float*)d_in[4];
    const float* bhd  = (const float*)d_in[5];
    const float* Wout = (const float*)d_in[6];
    const float* bout = (const float*)d_in[7];
    float* Y = (float*)d_out;

    cudaFuncSetAttribute(ntm_kernel, cudaFuncAttributeMaxDynamicSharedMemorySize,
                         SMEM_BYTES);
    ntm_kernel<<<GRID, NT, SMEM_BYTES>>>(X, Wih, Whh, bl, Whd, bhd, Wout, bout, Y);
}